// round 14
// baseline (speedup 1.0000x reference)
#include <cuda_runtime.h>
#include <cuda_bf16.h>
#include <cstdint>
#include <math.h>

#define Bq 8
#define Nq 20000
#define Dq 1024
#define NT (Bq*Nq)      // 160000 tiles
#define KSEL 10
#define MT 128          // tiles per CTA (k1)
#define KC 16           // K per chunk
#define NCHK 64         // chunks
#define SPL 10          // score slices per batch (k2a)
#define SLE (Nq/SPL)    // 2000 elements per slice

static __device__ float g_scores[NT];
static __device__ float g_outv[NT*32];
static __device__ unsigned long long g_candB[Bq][SPL][KSEL];
static __device__ unsigned long long g_candT[Bq][SPL][KSEL];

// 32-B row swizzle (validated in R11): flip bit4 by bit7
#define SWZ32(o) ((o) ^ (((o) >> 3) & 0x10))

// float smem offsets (weights region, k1)
#define F_W2  0
#define F_W3  256
#define F_B1  512
#define F_B2  544
#define F_B3  552
#define F_WSC 584
#define F_BSC 616
// byte offsets (stage region, k1): rows are 32 B (16 bf16)
#define O_STAGE 4096
#define STG_SZ  10240
#define S_AH 0          // 128 rows x 32 B = 4 KB
#define S_AL 4096
#define S_BH 8192       // 32 rows x 32 B = 1 KB
#define S_BL 9216
#define SMEM_K1 (O_STAGE + 2*STG_SZ)   // 24576 B -> 6 CTAs/SM

// k2b dynamic smem: Wc1 staged as floats
#define SMEM_K2B (22144*4 + 1024)      // 89600 B

__device__ __forceinline__ uint32_t s2u(const void* p){
    uint32_t a;
    asm("{ .reg .u64 t; cvta.to.shared.u64 t, %1; cvt.u32.u64 %0, t; }" : "=r"(a) : "l"(p));
    return a;
}
// pack {bf16(x1):bf16(x0)} (x0 in low half)
__device__ __forceinline__ uint32_t bf2pack(float x0, float x1){
    uint32_t r; asm("cvt.rn.bf16x2.f32 %0, %1, %2;" : "=r"(r) : "f"(x1), "f"(x0)); return r;
}
__device__ __forceinline__ void cp16(uint32_t dsts, const void* src){
    asm volatile("cp.async.cg.shared.global [%0], [%1], 16;" :: "r"(dsts), "l"(src) : "memory");
}
__device__ __forceinline__ void ldsm4(uint32_t a, uint32_t r[4]){
    asm volatile("ldmatrix.sync.aligned.m8n8.x4.shared.b16 {%0,%1,%2,%3}, [%4];"
        : "=r"(r[0]), "=r"(r[1]), "=r"(r[2]), "=r"(r[3]) : "r"(a));
}
__device__ __forceinline__ void mma16816(float c[4], const uint32_t a[4], uint32_t b0, uint32_t b1){
    asm volatile("mma.sync.aligned.m16n8k16.row.col.f32.bf16.bf16.f32 "
        "{%0,%1,%2,%3}, {%4,%5,%6,%7}, {%8,%9}, {%0,%1,%2,%3};"
        : "+f"(c[0]), "+f"(c[1]), "+f"(c[2]), "+f"(c[3])
        : "r"(a[0]), "r"(a[1]), "r"(a[2]), "r"(a[3]), "r"(b0), "r"(b1));
}

// ======= Kernel 1: bf16-split HMMA GEMM (M=128,N=32,K=1024) =======================
// 4 warps/CTA, warp tile M=32 x N=32 (halves LDSM-B), 6 CTAs/SM, KC=16.
__global__ __launch_bounds__(128, 6)
void k1(const float* __restrict__ x,  const float* __restrict__ W1, const float* __restrict__ b1,
        const float* __restrict__ W2, const float* __restrict__ b2,
        const float* __restrict__ W3, const float* __restrict__ b3,
        const float* __restrict__ Wsc, const float* __restrict__ bsc)
{
    extern __shared__ char smem[];
    float* sf = (float*)smem;
    const uint32_t sb = s2u(smem);
    const int tid = threadIdx.x;
    const int wid = tid >> 5;      // 0..3
    const int lid = tid & 31;
    const int t0  = blockIdx.x * MT;

    for (int i = tid; i < 256; i += 128){ sf[F_W2 + i] = W2[i]; sf[F_W3 + i] = W3[i]; }
    if (tid < 32){ sf[F_B1 + tid] = b1[tid]; sf[F_B3 + tid] = b3[tid]; sf[F_WSC + tid] = Wsc[tid]; }
    if (tid < 8) sf[F_B2 + tid] = b2[tid];
    if (tid == 0) sf[F_BSC] = bsc[0];

    float4 ra[4], rw;

    // load chunk c: x 128 rows x 16 cols (4 float4/thread), W 32x16 (1 float4/thread)
    auto LD = [&](int c){
        const int k0c = c * KC;
#pragma unroll
        for (int j = 0; j < 4; j++){
            int f = tid + 128*j; int row = f >> 2, q = f & 3;
            ra[j] = __ldg((const float4*)(x + (size_t)(t0 + row) * Dq + k0c) + q);
        }
        rw = __ldg((const float4*)(W1 + (size_t)(tid >> 2) * Dq + k0c) + (tid & 3));
    };
    // split fp32 -> bf16 hi/lo, store SW32-swizzled
    auto ST = [&](int buf){
        const uint32_t stg = O_STAGE + buf * STG_SZ;
#pragma unroll
        for (int j = 0; j < 4; j++){
            int f = tid + 128*j; int row = f >> 2, q = f & 3;
            float4 v = ra[j];
            uint32_t h0 = bf2pack(v.x, v.y), h1 = bf2pack(v.z, v.w);
            float hx = __uint_as_float(h0 << 16), hy = __uint_as_float(h0 & 0xffff0000u);
            float hz = __uint_as_float(h1 << 16), hw = __uint_as_float(h1 & 0xffff0000u);
            uint32_t l0 = bf2pack(v.x - hx, v.y - hy), l1 = bf2pack(v.z - hz, v.w - hw);
            uint32_t bo = SWZ32((uint32_t)(row * 32 + q * 8));
            *(uint2*)(smem + stg + S_AH + bo) = make_uint2(h0, h1);
            *(uint2*)(smem + stg + S_AL + bo) = make_uint2(l0, l1);
        }
        {
            int row = tid >> 2, q = tid & 3;
            float4 v = rw;
            uint32_t h0 = bf2pack(v.x, v.y), h1 = bf2pack(v.z, v.w);
            float hx = __uint_as_float(h0 << 16), hy = __uint_as_float(h0 & 0xffff0000u);
            float hz = __uint_as_float(h1 << 16), hw = __uint_as_float(h1 & 0xffff0000u);
            uint32_t l0 = bf2pack(v.x - hx, v.y - hy), l1 = bf2pack(v.z - hz, v.w - hw);
            uint32_t bo = SWZ32((uint32_t)(row * 32 + q * 8));
            *(uint2*)(smem + stg + S_BH + bo) = make_uint2(h0, h1);
            *(uint2*)(smem + stg + S_BL + bo) = make_uint2(l0, l1);
        }
    };

    LD(0);
    ST(0);
    __syncthreads();

    float acc[2][4][4];
#pragma unroll
    for (int m = 0; m < 2; m++)
#pragma unroll
        for (int i = 0; i < 4; i++)
#pragma unroll
            for (int j = 0; j < 4; j++) acc[m][i][j] = 0.f;

    const int bn = (lid & 7) + ((lid >> 4) * 8);
    const uint32_t kbyte = (uint32_t)(((lid >> 3) & 1) * 16);

    for (int c = 0; c < NCHK; c++){
        if (c + 1 < NCHK) LD(c + 1);
        const uint32_t stg = O_STAGE + (c & 1) * STG_SZ;
        uint32_t ah[2][4], al[2][4];
#pragma unroll
        for (int m = 0; m < 2; m++){
            uint32_t ab = SWZ32((uint32_t)((wid*32 + m*16 + (lid & 15)) * 32 + (lid >> 4) * 16));
            ldsm4(sb + stg + S_AH + ab, ah[m]);
            ldsm4(sb + stg + S_AL + ab, al[m]);
        }
#pragma unroll
        for (int nb2 = 0; nb2 < 2; nb2++){
            uint32_t bh[4], bl[4];
            uint32_t bb = SWZ32((uint32_t)((nb2*16 + bn) * 32) + kbyte);
            ldsm4(sb + stg + S_BH + bb, bh);
            ldsm4(sb + stg + S_BL + bb, bl);
#pragma unroll
            for (int m = 0; m < 2; m++){
                mma16816(acc[m][nb2*2],   ah[m], bh[0], bh[1]);
                mma16816(acc[m][nb2*2+1], ah[m], bh[2], bh[3]);
                mma16816(acc[m][nb2*2],   ah[m], bl[0], bl[1]);
                mma16816(acc[m][nb2*2+1], ah[m], bl[2], bl[3]);
                mma16816(acc[m][nb2*2],   al[m], bh[0], bh[1]);
                mma16816(acc[m][nb2*2+1], al[m], bh[2], bh[3]);
            }
        }
        if (c + 1 < NCHK){
            ST((c + 1) & 1);
            __syncthreads();
        }
    }
    // h1s (16.9 KB from O_STAGE) overlaps stage buf1 — MUST drain all warps' final
    // ldsm reads of buf1 (chunk 63) before overwriting. This barrier was the R13 bug.
    __syncthreads();

    // h1 (pre-bias) -> smem
    float* h1s = (float*)(smem + O_STAGE);
    {
        const int gid = lid >> 2, qd = lid & 3;
#pragma unroll
        for (int m = 0; m < 2; m++){
            const int r0 = wid*32 + m*16 + gid, r1 = r0 + 8;
#pragma unroll
            for (int nbl = 0; nbl < 4; nbl++){
                h1s[r0*33 + nbl*8 + qd*2 + 0] = acc[m][nbl][0];
                h1s[r0*33 + nbl*8 + qd*2 + 1] = acc[m][nbl][1];
                h1s[r1*33 + nbl*8 + qd*2 + 0] = acc[m][nbl][2];
                h1s[r1*33 + nbl*8 + qd*2 + 1] = acc[m][nbl][3];
            }
        }
    }
    __syncthreads();

    {
        const int m = tid;             // 128 threads = 128 rows
        const size_t t = (size_t)t0 + m;
        float hv[32];
#pragma unroll
        for (int h = 0; h < 32; h++){
            float v = h1s[m*33 + h] + sf[F_B1 + h];
            hv[h] = v > 0.f ? v : 0.f;
        }
        float h2[8];
#pragma unroll
        for (int g = 0; g < 8; g++){
            float s = sf[F_B2 + g];
#pragma unroll
            for (int h = 0; h < 32; h++) s = fmaf(sf[F_W2 + g*32 + h], hv[h], s);
            h2[g] = s > 0.f ? s : 0.f;
        }
        float sc = sf[F_BSC];
#pragma unroll
        for (int h4 = 0; h4 < 8; h4++){
            float4 o4; float* op = &o4.x;
#pragma unroll
            for (int kk = 0; kk < 4; kk++){
                const int h = h4*4 + kk;
                float s = sf[F_B3 + h];
#pragma unroll
                for (int g = 0; g < 8; g++) s = fmaf(sf[F_W3 + h*8 + g], h2[g], s);
                s = s > 0.f ? s : 0.f;
                op[kk] = s;
                sc = fmaf(sf[F_WSC + h], s, sc);
            }
            *(float4*)(&g_outv[t*32 + h4*4]) = o4;
        }
        g_scores[t] = sc > 0.f ? sc : 0.f;
    }
}

// ======= Kernel 2a: slice-local stable top/bottom-10 candidates ===================
// Key = (score_bits << 32) | index == jnp.argsort stable (score, index) order.
__global__ __launch_bounds__(256) void k2a(){
    const int bx = blockIdx.x;
    const int b = bx / SPL, sl = bx % SPL;
    const int tid = threadIdx.x, lane = tid & 31, warp = tid >> 5;  // 8 warps
    __shared__ unsigned long long wred[8], swin, skB[KSEL], skT[KSEL];

    unsigned long long bot[KSEL], top[KSEL];
#pragma unroll
    for (int j = 0; j < KSEL; j++){ bot[j] = ~0ull; top[j] = 0ull; }

    const float4* sp = (const float4*)(g_scores + (size_t)b * Nq + sl * SLE);
    for (int v = tid; v < SLE/4; v += 256){
        float4 s4 = sp[v];
        float ss[4] = {s4.x, s4.y, s4.z, s4.w};
#pragma unroll
        for (int e = 0; e < 4; e++){
            unsigned long long key = ((unsigned long long)__float_as_uint(ss[e]) << 32)
                                   | (unsigned)(sl*SLE + v*4 + e);
            if (key < bot[KSEL-1]){
                bot[KSEL-1] = key;
#pragma unroll
                for (int j = KSEL-1; j > 0; j--){
                    unsigned long long a0 = bot[j-1], a1 = bot[j];
                    bot[j-1] = a0 < a1 ? a0 : a1;
                    bot[j]   = a0 < a1 ? a1 : a0;
                }
            }
            if (key > top[KSEL-1]){
                top[KSEL-1] = key;
#pragma unroll
                for (int j = KSEL-1; j > 0; j--){
                    unsigned long long a0 = top[j-1], a1 = top[j];
                    top[j-1] = a0 > a1 ? a0 : a1;
                    top[j]   = a0 > a1 ? a1 : a0;
                }
            }
        }
    }
    __syncthreads();

    for (int i = 0; i < KSEL; i++){
        unsigned long long v = bot[0];
#pragma unroll
        for (int o = 16; o > 0; o >>= 1){
            unsigned long long u = __shfl_down_sync(0xffffffffu, v, o);
            if (u < v) v = u;
        }
        if (lane == 0) wred[warp] = v;
        __syncthreads();
        if (warp == 0){
            unsigned long long w = (lane < 8) ? wred[lane] : ~0ull;
#pragma unroll
            for (int o = 4; o > 0; o >>= 1){
                unsigned long long u = __shfl_down_sync(0xffffffffu, w, o);
                if (u < w) w = u;
            }
            if (lane == 0){ swin = w; skB[i] = w; }
        }
        __syncthreads();
        if (bot[0] == swin){
#pragma unroll
            for (int j = 0; j < KSEL-1; j++) bot[j] = bot[j+1];
            bot[KSEL-1] = ~0ull;
        }
        __syncthreads();
    }
    for (int i = 0; i < KSEL; i++){
        unsigned long long v = top[0];
#pragma unroll
        for (int o = 16; o > 0; o >>= 1){
            unsigned long long u = __shfl_down_sync(0xffffffffu, v, o);
            if (u > v) v = u;
        }
        if (lane == 0) wred[warp] = v;
        __syncthreads();
        if (warp == 0){
            unsigned long long w = (lane < 8) ? wred[lane] : 0ull;
#pragma unroll
            for (int o = 4; o > 0; o >>= 1){
                unsigned long long u = __shfl_down_sync(0xffffffffu, w, o);
                if (u > w) w = u;
            }
            if (lane == 0){ swin = w; skT[i] = w; }
        }
        __syncthreads();
        if (top[0] == swin){
#pragma unroll
            for (int j = 0; j < KSEL-1; j++) top[j] = top[j+1];
            top[KSEL-1] = 0ull;
        }
        __syncthreads();
    }
    if (tid < KSEL){ g_candB[b][sl][tid] = skB[tid]; g_candT[b][sl][tid] = skT[tid]; }
}

// ======= Kernel 2b: merge candidates + gather features + classifier ===============
// Wc1 (88.6 KB) prefetched to dynamic smem via cp.async at entry — DRAM latency
// overlaps the 20-round merge phase; classifier L1 runs from LDS.
__global__ __launch_bounds__(256) void k2b(
    const float* __restrict__ Wc1, const float* __restrict__ bc1,
    const float* __restrict__ Wc2, const float* __restrict__ bc2,
    const float* __restrict__ Wc3, const float* __restrict__ bc3,
    float* __restrict__ outp)
{
    extern __shared__ float dsm[];
    float* sWc1 = dsm;                 // 22144 floats
    const int b = blockIdx.x, tid = threadIdx.x;
    const int lane = tid & 31, warp = tid >> 5;   // 8 warps
    __shared__ unsigned long long wred[8], swin, selkey[20];
    __shared__ float feat[692], z1[32], z2[32];

    // prefetch Wc1: 5536 x 16B segments
    {
        const uint32_t dst = s2u(sWc1);
        for (int i = tid; i < 5536; i += 256)
            cp16(dst + i*16, Wc1 + i*4);
        asm volatile("cp.async.commit_group;" ::: "memory");
    }

    unsigned long long kb = (tid < SPL*KSEL) ? g_candB[b][tid/KSEL][tid%KSEL] : ~0ull;
    unsigned long long kt = (tid < SPL*KSEL) ? g_candT[b][tid/KSEL][tid%KSEL] : 0ull;

    for (int i = 0; i < KSEL; i++){
        unsigned long long v = kb;
#pragma unroll
        for (int o = 16; o > 0; o >>= 1){
            unsigned long long u = __shfl_down_sync(0xffffffffu, v, o);
            if (u < v) v = u;
        }
        if (lane == 0) wred[warp] = v;
        __syncthreads();
        if (warp == 0){
            unsigned long long w = (lane < 8) ? wred[lane] : ~0ull;
#pragma unroll
            for (int o = 4; o > 0; o >>= 1){
                unsigned long long u = __shfl_down_sync(0xffffffffu, w, o);
                if (u < w) w = u;
            }
            if (lane == 0){ swin = w; selkey[i] = w; }
        }
        __syncthreads();
        if (kb == swin) kb = ~0ull;
        __syncthreads();
    }
    for (int i = 0; i < KSEL; i++){
        unsigned long long v = kt;
#pragma unroll
        for (int o = 16; o > 0; o >>= 1){
            unsigned long long u = __shfl_down_sync(0xffffffffu, v, o);
            if (u > v) v = u;
        }
        if (lane == 0) wred[warp] = v;
        __syncthreads();
        if (warp == 0){
            unsigned long long w = (lane < 8) ? wred[lane] : 0ull;
#pragma unroll
            for (int o = 4; o > 0; o >>= 1){
                unsigned long long u = __shfl_down_sync(0xffffffffu, w, o);
                if (u > w) w = u;
            }
            if (lane == 0){ swin = w; selkey[19-i] = w; }
        }
        __syncthreads();
        if (kt == swin) kt = 0ull;
        __syncthreads();
    }

    // features: [g_sc(0..19) | avg(20..51) | g_flat(52..691): 52 + h*20 + j]
    for (int i = tid; i < 640; i += 256){
        int j = i >> 5, h = i & 31;
        int n = (int)(selkey[j] & 0xFFFFFFFFull);
        feat[52 + h*20 + j] = g_outv[((size_t)b*Nq + n)*32 + h];
    }
    if (tid < 20) feat[tid] = __uint_as_float((unsigned)(selkey[tid] >> 32));
    __syncthreads();
    if (tid < 32){
        float s = 0.f;
#pragma unroll
        for (int j = 0; j < 20; j++) s += feat[52 + tid*20 + j];
        feat[20 + tid] = s * (1.f/20.f);
    }
    asm volatile("cp.async.wait_group 0;" ::: "memory");
    __syncthreads();

    // classifier layer 1 from smem: 8 threads per output + shfl reduce
    {
        int o = tid >> 3, p = tid & 7;
        const float* wr = sWc1 + o * 692;
        float s = 0.f;
        for (int i = p; i < 692; i += 8) s = fmaf(wr[i], feat[i], s);
        s += __shfl_xor_sync(0xffffffffu, s, 1);
        s += __shfl_xor_sync(0xffffffffu, s, 2);
        s += __shfl_xor_sync(0xffffffffu, s, 4);
        if (p == 0){ s += bc1[o]; z1[o] = s > 0.f ? s : 0.f; }
    }
    __syncthreads();
    if (tid < 32){
        float s = bc2[tid];
#pragma unroll
        for (int i = 0; i < 32; i++) s = fmaf(Wc2[tid*32+i], z1[i], s);
        z2[tid] = s > 0.f ? s : 0.f;
    }
    __syncthreads();
    if (tid == 0){
        float s = bc3[0];
#pragma unroll
        for (int i = 0; i < 32; i++) s = fmaf(Wc3[i], z2[i], s);
        outp[b] = 1.f / (1.f + expf(-s));
    }
}

extern "C" void kernel_launch(void* const* d_in, const int* in_sizes, int n_in,
                              void* d_out, int out_size) {
    const float* x   = (const float*)d_in[0];
    const float* W1  = (const float*)d_in[1];
    const float* b1  = (const float*)d_in[2];
    const float* W2  = (const float*)d_in[3];
    const float* b2  = (const float*)d_in[4];
    const float* W3  = (const float*)d_in[5];
    const float* b3  = (const float*)d_in[6];
    const float* Wsc = (const float*)d_in[7];
    const float* bsc = (const float*)d_in[8];
    const float* Wc1 = (const float*)d_in[9];
    const float* bc1 = (const float*)d_in[10];
    const float* Wc2 = (const float*)d_in[11];
    const float* bc2 = (const float*)d_in[12];
    const float* Wc3 = (const float*)d_in[13];
    const float* bc3 = (const float*)d_in[14];
    float* outp = (float*)d_out;

    cudaFuncSetAttribute(k1,  cudaFuncAttributeMaxDynamicSharedMemorySize, SMEM_K1);
    cudaFuncSetAttribute(k2b, cudaFuncAttributeMaxDynamicSharedMemorySize, SMEM_K2B);
    k1<<<NT/MT, 128, SMEM_K1>>>(x, W1, b1, W2, b2, W3, b3, Wsc, bsc);
    k2a<<<Bq*SPL, 256>>>();
    k2b<<<Bq, 256, SMEM_K2B>>>(Wc1, bc1, Wc2, bc2, Wc3, bc3, outp);
}

// round 15
// speedup vs baseline: 1.2291x; 1.2291x over previous
#include <cuda_runtime.h>
#include <cuda_bf16.h>
#include <cstdint>
#include <math.h>

#define Bq 8
#define Nq 20000
#define Dq 1024
#define NT (Bq*Nq)      // 160000 tiles
#define KSEL 10
#define MT 128          // tiles per CTA (k1)
#define KC 32           // K per chunk
#define NCHK 32         // chunks
#define SPL 10          // score slices per batch (k2a)
#define SLE (Nq/SPL)    // 2000 elements per slice

static __device__ float g_scores[NT];
static __device__ float g_outv[NT*32];
static __device__ unsigned long long g_candB[Bq][SPL][KSEL];
static __device__ unsigned long long g_candT[Bq][SPL][KSEL];

#define SWZ64(o) ((o) ^ (((o) >> 3) & 0x30))

// float smem offsets (weights region, k1)
#define F_W2  0
#define F_W3  256
#define F_B1  512
#define F_B2  544
#define F_B3  552
#define F_WSC 584
#define F_BSC 616
// byte offsets (stage region, k1): rows are 64 B (32 bf16), SW64 atoms
#define O_STAGE 4096
#define STG_SZ  20480
#define S_AH 0          // 128 rows x 64 B = 8 KB
#define S_AL 8192
#define S_BH 16384      // 32 rows x 64 B = 2 KB
#define S_BL 18432
#define SMEM_K1 (O_STAGE + 2*STG_SZ)   // 45056 B -> 3 CTAs/SM (smem)

// k2b dynamic smem: Wc1 staged as floats
#define SMEM_K2B (22144*4 + 1024)      // 89600 B

__device__ __forceinline__ uint32_t s2u(const void* p){
    uint32_t a;
    asm("{ .reg .u64 t; cvta.to.shared.u64 t, %1; cvt.u32.u64 %0, t; }" : "=r"(a) : "l"(p));
    return a;
}
// pack {bf16(x1):bf16(x0)} (x0 in low half)
__device__ __forceinline__ uint32_t bf2pack(float x0, float x1){
    uint32_t r; asm("cvt.rn.bf16x2.f32 %0, %1, %2;" : "=r"(r) : "f"(x1), "f"(x0)); return r;
}
__device__ __forceinline__ void cp16(uint32_t dsts, const void* src){
    asm volatile("cp.async.cg.shared.global [%0], [%1], 16;" :: "r"(dsts), "l"(src) : "memory");
}
__device__ __forceinline__ void ldsm4(uint32_t a, uint32_t r[4]){
    asm volatile("ldmatrix.sync.aligned.m8n8.x4.shared.b16 {%0,%1,%2,%3}, [%4];"
        : "=r"(r[0]), "=r"(r[1]), "=r"(r[2]), "=r"(r[3]) : "r"(a));
}
__device__ __forceinline__ void mma16816(float c[4], const uint32_t a[4], uint32_t b0, uint32_t b1){
    asm volatile("mma.sync.aligned.m16n8k16.row.col.f32.bf16.bf16.f32 "
        "{%0,%1,%2,%3}, {%4,%5,%6,%7}, {%8,%9}, {%0,%1,%2,%3};"
        : "+f"(c[0]), "+f"(c[1]), "+f"(c[2]), "+f"(c[3])
        : "r"(a[0]), "r"(a[1]), "r"(a[2]), "r"(a[3]), "r"(b0), "r"(b1));
}

// ======= Kernel 1: bf16-split HMMA GEMM (M=128,N=32,K=1024) =======================
// k-split warp specialization: warps 0-3 = k-step 0, warps 4-7 = k-step 1, each
// with an M=32 x N=32 tile over the same 128 rows. Halves LDSM-B traffic at
// unchanged KC=32 / 3 CTAs/SM. Partials merged in epilogue.
__global__ __launch_bounds__(256, 3)
void k1(const float* __restrict__ x,  const float* __restrict__ W1, const float* __restrict__ b1,
        const float* __restrict__ W2, const float* __restrict__ b2,
        const float* __restrict__ W3, const float* __restrict__ b3,
        const float* __restrict__ Wsc, const float* __restrict__ bsc)
{
    extern __shared__ char smem[];
    float* sf = (float*)smem;
    const uint32_t sb = s2u(smem);
    const int tid = threadIdx.x;
    const int wid = tid >> 5;
    const int lid = tid & 31;
    const int t0  = blockIdx.x * MT;

    for (int i = tid; i < 256; i += 256){ sf[F_W2 + i] = W2[i]; sf[F_W3 + i] = W3[i]; }
    if (tid < 32){ sf[F_B1 + tid] = b1[tid]; sf[F_B3 + tid] = b3[tid]; sf[F_WSC + tid] = Wsc[tid]; }
    if (tid < 8) sf[F_B2 + tid] = b2[tid];
    if (tid == 0) sf[F_BSC] = bsc[0];

    float4 ra[4], rw;

    // load chunk c: x 128 rows x 32 cols (4 float4/thread), W 32 rows x 32 (1 float4)
    auto LD = [&](int c){
        const int k0c = c * KC;
#pragma unroll
        for (int j = 0; j < 4; j++){
            int f = tid + 256*j; int row = f >> 3, q = f & 7;
            ra[j] = __ldg((const float4*)(x + (size_t)(t0 + row) * Dq + k0c) + q);
        }
        rw = __ldg((const float4*)(W1 + (size_t)(tid >> 3) * Dq + k0c) + (tid & 7));
    };
    // split fp32 -> bf16 hi/lo, store SW64-swizzled
    auto ST = [&](int buf){
        const uint32_t stg = O_STAGE + buf * STG_SZ;
#pragma unroll
        for (int j = 0; j < 4; j++){
            int f = tid + 256*j; int row = f >> 3, q = f & 7;
            float4 v = ra[j];
            uint32_t h0 = bf2pack(v.x, v.y), h1 = bf2pack(v.z, v.w);
            float hx = __uint_as_float(h0 << 16), hy = __uint_as_float(h0 & 0xffff0000u);
            float hz = __uint_as_float(h1 << 16), hw = __uint_as_float(h1 & 0xffff0000u);
            uint32_t l0 = bf2pack(v.x - hx, v.y - hy), l1 = bf2pack(v.z - hz, v.w - hw);
            uint32_t bo = SWZ64((uint32_t)(row * 64 + q * 8));
            *(uint2*)(smem + stg + S_AH + bo) = make_uint2(h0, h1);
            *(uint2*)(smem + stg + S_AL + bo) = make_uint2(l0, l1);
        }
        {
            int row = tid >> 3, q = tid & 7;
            float4 v = rw;
            uint32_t h0 = bf2pack(v.x, v.y), h1 = bf2pack(v.z, v.w);
            float hx = __uint_as_float(h0 << 16), hy = __uint_as_float(h0 & 0xffff0000u);
            float hz = __uint_as_float(h1 << 16), hw = __uint_as_float(h1 & 0xffff0000u);
            uint32_t l0 = bf2pack(v.x - hx, v.y - hy), l1 = bf2pack(v.z - hz, v.w - hw);
            uint32_t bo = SWZ64((uint32_t)(row * 64 + q * 8));
            *(uint2*)(smem + stg + S_BH + bo) = make_uint2(h0, h1);
            *(uint2*)(smem + stg + S_BL + bo) = make_uint2(l0, l1);
        }
    };

    LD(0);
    ST(0);
    __syncthreads();

    float acc[2][4][4];
#pragma unroll
    for (int m = 0; m < 2; m++)
#pragma unroll
        for (int i = 0; i < 4; i++)
#pragma unroll
            for (int j = 0; j < 4; j++) acc[m][i][j] = 0.f;

    const int mw = (wid & 3) * 32;     // warp's M base (0/32/64/96)
    const int ks = wid >> 2;           // warp's k-step (0 or 1)
    const int bn = (lid & 7) + ((lid >> 4) * 8);
    const uint32_t kb = (uint32_t)(ks * 32 + ((lid >> 3) & 1) * 16);

    for (int c = 0; c < NCHK; c++){
        if (c + 1 < NCHK) LD(c + 1);
        const uint32_t stg = O_STAGE + (c & 1) * STG_SZ;
        uint32_t ah[2][4], al[2][4];
#pragma unroll
        for (int m = 0; m < 2; m++){
            uint32_t ab = SWZ64((uint32_t)((mw + m*16 + (lid & 15)) * 64 + ks * 32 + (lid >> 4) * 16));
            ldsm4(sb + stg + S_AH + ab, ah[m]);
            ldsm4(sb + stg + S_AL + ab, al[m]);
        }
#pragma unroll
        for (int nb2 = 0; nb2 < 2; nb2++){
            uint32_t bh[4], bl[4];
            uint32_t bb = SWZ64((uint32_t)((nb2*16 + bn) * 64) + kb);
            ldsm4(sb + stg + S_BH + bb, bh);
            ldsm4(sb + stg + S_BL + bb, bl);
#pragma unroll
            for (int m = 0; m < 2; m++){
                mma16816(acc[m][nb2*2],   ah[m], bh[0], bh[1]);
                mma16816(acc[m][nb2*2+1], ah[m], bh[2], bh[3]);
                mma16816(acc[m][nb2*2],   ah[m], bl[0], bl[1]);
                mma16816(acc[m][nb2*2+1], ah[m], bl[2], bl[3]);
                mma16816(acc[m][nb2*2],   al[m], bh[0], bh[1]);
                mma16816(acc[m][nb2*2+1], al[m], bh[2], bh[3]);
            }
        }
        if (c + 1 < NCHK){
            ST((c + 1) & 1);
            __syncthreads();
        }
    }
    // stage region is about to be reused for partial sums — drain all warps' final
    // ldsm reads of the last buffer first (the R13 race).
    __syncthreads();

    // two partial-sum buffers (k-step 0 and 1), both inside the 40 KB stage region
    float* h1a = (float*)(smem + O_STAGE);            // 16896 B
    float* h1b = (float*)(smem + O_STAGE + 17024);    // 16896 B (33920 <= 40960)
    {
        float* dst = (ks == 0) ? h1a : h1b;
        const int gid = lid >> 2, qd = lid & 3;
#pragma unroll
        for (int m = 0; m < 2; m++){
            const int r0 = mw + m*16 + gid, r1 = r0 + 8;
#pragma unroll
            for (int nbl = 0; nbl < 4; nbl++){
                dst[r0*33 + nbl*8 + qd*2 + 0] = acc[m][nbl][0];
                dst[r0*33 + nbl*8 + qd*2 + 1] = acc[m][nbl][1];
                dst[r1*33 + nbl*8 + qd*2 + 0] = acc[m][nbl][2];
                dst[r1*33 + nbl*8 + qd*2 + 1] = acc[m][nbl][3];
            }
        }
    }
    __syncthreads();

    if (tid < MT){
        const int m = tid;
        const size_t t = (size_t)t0 + m;
        float hv[32];
#pragma unroll
        for (int h = 0; h < 32; h++){
            float v = h1a[m*33 + h] + h1b[m*33 + h] + sf[F_B1 + h];
            hv[h] = v > 0.f ? v : 0.f;
        }
        float h2[8];
#pragma unroll
        for (int g = 0; g < 8; g++){
            float s = sf[F_B2 + g];
#pragma unroll
            for (int h = 0; h < 32; h++) s = fmaf(sf[F_W2 + g*32 + h], hv[h], s);
            h2[g] = s > 0.f ? s : 0.f;
        }
        float sc = sf[F_BSC];
#pragma unroll
        for (int h4 = 0; h4 < 8; h4++){
            float4 o4; float* op = &o4.x;
#pragma unroll
            for (int kk = 0; kk < 4; kk++){
                const int h = h4*4 + kk;
                float s = sf[F_B3 + h];
#pragma unroll
                for (int g = 0; g < 8; g++) s = fmaf(sf[F_W3 + h*8 + g], h2[g], s);
                s = s > 0.f ? s : 0.f;
                op[kk] = s;
                sc = fmaf(sf[F_WSC + h], s, sc);
            }
            *(float4*)(&g_outv[t*32 + h4*4]) = o4;
        }
        g_scores[t] = sc > 0.f ? sc : 0.f;
    }
}

// ======= Kernel 2a: slice-local stable top/bottom-10 candidates ===================
// Key = (score_bits << 32) | index == jnp.argsort stable (score, index) order.
__global__ __launch_bounds__(256) void k2a(){
    const int bx = blockIdx.x;
    const int b = bx / SPL, sl = bx % SPL;
    const int tid = threadIdx.x, lane = tid & 31, warp = tid >> 5;  // 8 warps
    __shared__ unsigned long long wred[8], swin, skB[KSEL], skT[KSEL];

    unsigned long long bot[KSEL], top[KSEL];
#pragma unroll
    for (int j = 0; j < KSEL; j++){ bot[j] = ~0ull; top[j] = 0ull; }

    const float4* sp = (const float4*)(g_scores + (size_t)b * Nq + sl * SLE);
    for (int v = tid; v < SLE/4; v += 256){
        float4 s4 = sp[v];
        float ss[4] = {s4.x, s4.y, s4.z, s4.w};
#pragma unroll
        for (int e = 0; e < 4; e++){
            unsigned long long key = ((unsigned long long)__float_as_uint(ss[e]) << 32)
                                   | (unsigned)(sl*SLE + v*4 + e);
            if (key < bot[KSEL-1]){
                bot[KSEL-1] = key;
#pragma unroll
                for (int j = KSEL-1; j > 0; j--){
                    unsigned long long a0 = bot[j-1], a1 = bot[j];
                    bot[j-1] = a0 < a1 ? a0 : a1;
                    bot[j]   = a0 < a1 ? a1 : a0;
                }
            }
            if (key > top[KSEL-1]){
                top[KSEL-1] = key;
#pragma unroll
                for (int j = KSEL-1; j > 0; j--){
                    unsigned long long a0 = top[j-1], a1 = top[j];
                    top[j-1] = a0 > a1 ? a0 : a1;
                    top[j]   = a0 > a1 ? a1 : a0;
                }
            }
        }
    }
    __syncthreads();

    for (int i = 0; i < KSEL; i++){
        unsigned long long v = bot[0];
#pragma unroll
        for (int o = 16; o > 0; o >>= 1){
            unsigned long long u = __shfl_down_sync(0xffffffffu, v, o);
            if (u < v) v = u;
        }
        if (lane == 0) wred[warp] = v;
        __syncthreads();
        if (warp == 0){
            unsigned long long w = (lane < 8) ? wred[lane] : ~0ull;
#pragma unroll
            for (int o = 4; o > 0; o >>= 1){
                unsigned long long u = __shfl_down_sync(0xffffffffu, w, o);
                if (u < w) w = u;
            }
            if (lane == 0){ swin = w; skB[i] = w; }
        }
        __syncthreads();
        if (bot[0] == swin){
#pragma unroll
            for (int j = 0; j < KSEL-1; j++) bot[j] = bot[j+1];
            bot[KSEL-1] = ~0ull;
        }
        __syncthreads();
    }
    for (int i = 0; i < KSEL; i++){
        unsigned long long v = top[0];
#pragma unroll
        for (int o = 16; o > 0; o >>= 1){
            unsigned long long u = __shfl_down_sync(0xffffffffu, v, o);
            if (u > v) v = u;
        }
        if (lane == 0) wred[warp] = v;
        __syncthreads();
        if (warp == 0){
            unsigned long long w = (lane < 8) ? wred[lane] : 0ull;
#pragma unroll
            for (int o = 4; o > 0; o >>= 1){
                unsigned long long u = __shfl_down_sync(0xffffffffu, w, o);
                if (u > w) w = u;
            }
            if (lane == 0){ swin = w; skT[i] = w; }
        }
        __syncthreads();
        if (top[0] == swin){
#pragma unroll
            for (int j = 0; j < KSEL-1; j++) top[j] = top[j+1];
            top[KSEL-1] = 0ull;
        }
        __syncthreads();
    }
    if (tid < KSEL){ g_candB[b][sl][tid] = skB[tid]; g_candT[b][sl][tid] = skT[tid]; }
}

// ======= Kernel 2b: merge candidates + gather features + classifier ===============
// Wc1 (88.6 KB) prefetched to dynamic smem via cp.async at entry — DRAM latency
// overlaps the 20-round merge phase; classifier L1 runs from LDS.
__global__ __launch_bounds__(256) void k2b(
    const float* __restrict__ Wc1, const float* __restrict__ bc1,
    const float* __restrict__ Wc2, const float* __restrict__ bc2,
    const float* __restrict__ Wc3, const float* __restrict__ bc3,
    float* __restrict__ outp)
{
    extern __shared__ float dsm[];
    float* sWc1 = dsm;                 // 22144 floats
    const int b = blockIdx.x, tid = threadIdx.x;
    const int lane = tid & 31, warp = tid >> 5;   // 8 warps
    __shared__ unsigned long long wred[8], swin, selkey[20];
    __shared__ float feat[692], z1[32], z2[32];

    // prefetch Wc1: 5536 x 16B segments
    {
        const uint32_t dst = s2u(sWc1);
        for (int i = tid; i < 5536; i += 256)
            cp16(dst + i*16, Wc1 + i*4);
        asm volatile("cp.async.commit_group;" ::: "memory");
    }

    unsigned long long kb = (tid < SPL*KSEL) ? g_candB[b][tid/KSEL][tid%KSEL] : ~0ull;
    unsigned long long kt = (tid < SPL*KSEL) ? g_candT[b][tid/KSEL][tid%KSEL] : 0ull;

    for (int i = 0; i < KSEL; i++){
        unsigned long long v = kb;
#pragma unroll
        for (int o = 16; o > 0; o >>= 1){
            unsigned long long u = __shfl_down_sync(0xffffffffu, v, o);
            if (u < v) v = u;
        }
        if (lane == 0) wred[warp] = v;
        __syncthreads();
        if (warp == 0){
            unsigned long long w = (lane < 8) ? wred[lane] : ~0ull;
#pragma unroll
            for (int o = 4; o > 0; o >>= 1){
                unsigned long long u = __shfl_down_sync(0xffffffffu, w, o);
                if (u < w) w = u;
            }
            if (lane == 0){ swin = w; selkey[i] = w; }
        }
        __syncthreads();
        if (kb == swin) kb = ~0ull;
        __syncthreads();
    }
    for (int i = 0; i < KSEL; i++){
        unsigned long long v = kt;
#pragma unroll
        for (int o = 16; o > 0; o >>= 1){
            unsigned long long u = __shfl_down_sync(0xffffffffu, v, o);
            if (u > v) v = u;
        }
        if (lane == 0) wred[warp] = v;
        __syncthreads();
        if (warp == 0){
            unsigned long long w = (lane < 8) ? wred[lane] : 0ull;
#pragma unroll
            for (int o = 4; o > 0; o >>= 1){
                unsigned long long u = __shfl_down_sync(0xffffffffu, w, o);
                if (u > w) w = u;
            }
            if (lane == 0){ swin = w; selkey[19-i] = w; }
        }
        __syncthreads();
        if (kt == swin) kt = 0ull;
        __syncthreads();
    }

    // features: [g_sc(0..19) | avg(20..51) | g_flat(52..691): 52 + h*20 + j]
    for (int i = tid; i < 640; i += 256){
        int j = i >> 5, h = i & 31;
        int n = (int)(selkey[j] & 0xFFFFFFFFull);
        feat[52 + h*20 + j] = g_outv[((size_t)b*Nq + n)*32 + h];
    }
    if (tid < 20) feat[tid] = __uint_as_float((unsigned)(selkey[tid] >> 32));
    __syncthreads();
    if (tid < 32){
        float s = 0.f;
#pragma unroll
        for (int j = 0; j < 20; j++) s += feat[52 + tid*20 + j];
        feat[20 + tid] = s * (1.f/20.f);
    }
    asm volatile("cp.async.wait_group 0;" ::: "memory");
    __syncthreads();

    // classifier layer 1 from smem: 8 threads per output + shfl reduce
    {
        int o = tid >> 3, p = tid & 7;
        const float* wr = sWc1 + o * 692;
        float s = 0.f;
        for (int i = p; i < 692; i += 8) s = fmaf(wr[i], feat[i], s);
        s += __shfl_xor_sync(0xffffffffu, s, 1);
        s += __shfl_xor_sync(0xffffffffu, s, 2);
        s += __shfl_xor_sync(0xffffffffu, s, 4);
        if (p == 0){ s += bc1[o]; z1[o] = s > 0.f ? s : 0.f; }
    }
    __syncthreads();
    if (tid < 32){
        float s = bc2[tid];
#pragma unroll
        for (int i = 0; i < 32; i++) s = fmaf(Wc2[tid*32+i], z1[i], s);
        z2[tid] = s > 0.f ? s : 0.f;
    }
    __syncthreads();
    if (tid == 0){
        float s = bc3[0];
#pragma unroll
        for (int i = 0; i < 32; i++) s = fmaf(Wc3[i], z2[i], s);
        outp[b] = 1.f / (1.f + expf(-s));
    }
}

extern "C" void kernel_launch(void* const* d_in, const int* in_sizes, int n_in,
                              void* d_out, int out_size) {
    const float* x   = (const float*)d_in[0];
    const float* W1  = (const float*)d_in[1];
    const float* b1  = (const float*)d_in[2];
    const float* W2  = (const float*)d_in[3];
    const float* b2  = (const float*)d_in[4];
    const float* W3  = (const float*)d_in[5];
    const float* b3  = (const float*)d_in[6];
    const float* Wsc = (const float*)d_in[7];
    const float* bsc = (const float*)d_in[8];
    const float* Wc1 = (const float*)d_in[9];
    const float* bc1 = (const float*)d_in[10];
    const float* Wc2 = (const float*)d_in[11];
    const float* bc2 = (const float*)d_in[12];
    const float* Wc3 = (const float*)d_in[13];
    const float* bc3 = (const float*)d_in[14];
    float* outp = (float*)d_out;

    cudaFuncSetAttribute(k1,  cudaFuncAttributeMaxDynamicSharedMemorySize, SMEM_K1);
    cudaFuncSetAttribute(k2b, cudaFuncAttributeMaxDynamicSharedMemorySize, SMEM_K2B);
    k1<<<NT/MT, 256, SMEM_K1>>>(x, W1, b1, W2, b2, W3, b3, Wsc, bsc);
    k2a<<<Bq*SPL, 256>>>();
    k2b<<<Bq, 256, SMEM_K2B>>>(Wc1, bc1, Wc2, bc2, Wc3, bc3, outp);
}

// round 17
// speedup vs baseline: 1.4042x; 1.1424x over previous
#include <cuda_runtime.h>
#include <cuda_bf16.h>
#include <cstdint>
#include <math.h>

#define Bq 8
#define Nq 20000
#define Dq 1024
#define NT (Bq*Nq)      // 160000 tiles
#define KSEL 10
#define MT 128          // tiles per CTA (k1)
#define KC 32           // K per chunk
#define NCHK 32         // chunks
#define SPL 10          // score slices per batch (k2a)
#define SLE (Nq/SPL)    // 2000 elements per slice

static __device__ float g_scores[NT];
static __device__ float g_outv[NT*32];
static __device__ unsigned long long g_candB[Bq][SPL][KSEL];
static __device__ unsigned long long g_candT[Bq][SPL][KSEL];

#define SWZ64(o) ((o) ^ (((o) >> 3) & 0x30))

// float smem offsets (weights region, k1)
#define F_W2  0
#define F_W3  256
#define F_B1  512
#define F_B2  544
#define F_B3  552
#define F_WSC 584
#define F_BSC 616
// byte offsets (stage region, k1): rows are 64 B (32 bf16), SW64 atoms
#define O_STAGE 4096
#define STG_SZ  20480
#define S_AH 0          // 128 rows x 64 B = 8 KB
#define S_AL 8192
#define S_BH 16384      // 32 rows x 64 B = 2 KB
#define S_BL 18432
#define SMEM_K1 (O_STAGE + 2*STG_SZ)   // 45056 B -> 3 CTAs/SM

// k2b dynamic smem: Wc1 staged as floats
#define SMEM_K2B (22144*4 + 1024)      // 89600 B

__device__ __forceinline__ uint32_t s2u(const void* p){
    uint32_t a;
    asm("{ .reg .u64 t; cvta.to.shared.u64 t, %1; cvt.u32.u64 %0, t; }" : "=r"(a) : "l"(p));
    return a;
}
// pack {bf16(x1):bf16(x0)} (x0 in low half)
__device__ __forceinline__ uint32_t bf2pack(float x0, float x1){
    uint32_t r; asm("cvt.rn.bf16x2.f32 %0, %1, %2;" : "=r"(r) : "f"(x1), "f"(x0)); return r;
}
__device__ __forceinline__ void cp16(uint32_t dsts, const void* src){
    asm volatile("cp.async.cg.shared.global [%0], [%1], 16;" :: "r"(dsts), "l"(src) : "memory");
}
__device__ __forceinline__ void ldsm4(uint32_t a, uint32_t r[4]){
    asm volatile("ldmatrix.sync.aligned.m8n8.x4.shared.b16 {%0,%1,%2,%3}, [%4];"
        : "=r"(r[0]), "=r"(r[1]), "=r"(r[2]), "=r"(r[3]) : "r"(a));
}
__device__ __forceinline__ void mma16816(float c[4], const uint32_t a[4], uint32_t b0, uint32_t b1){
    asm volatile("mma.sync.aligned.m16n8k16.row.col.f32.bf16.bf16.f32 "
        "{%0,%1,%2,%3}, {%4,%5,%6,%7}, {%8,%9}, {%0,%1,%2,%3};"
        : "+f"(c[0]), "+f"(c[1]), "+f"(c[2]), "+f"(c[3])
        : "r"(a[0]), "r"(a[1]), "r"(a[2]), "r"(a[3]), "r"(b0), "r"(b1));
}

// ======= Kernel 1: bf16-split HMMA GEMM (M=128,N=32,K=1024), 3 CTAs/SM ============
// Exact R12 configuration (validated best: 147.2 us).
__global__ __launch_bounds__(256, 3)
void k1(const float* __restrict__ x,  const float* __restrict__ W1, const float* __restrict__ b1,
        const float* __restrict__ W2, const float* __restrict__ b2,
        const float* __restrict__ W3, const float* __restrict__ b3,
        const float* __restrict__ Wsc, const float* __restrict__ bsc)
{
    extern __shared__ char smem[];
    float* sf = (float*)smem;
    const uint32_t sb = s2u(smem);
    const int tid = threadIdx.x;
    const int wid = tid >> 5;
    const int lid = tid & 31;
    const int t0  = blockIdx.x * MT;

    for (int i = tid; i < 256; i += 256){ sf[F_W2 + i] = W2[i]; sf[F_W3 + i] = W3[i]; }
    if (tid < 32){ sf[F_B1 + tid] = b1[tid]; sf[F_B3 + tid] = b3[tid]; sf[F_WSC + tid] = Wsc[tid]; }
    if (tid < 8) sf[F_B2 + tid] = b2[tid];
    if (tid == 0) sf[F_BSC] = bsc[0];

    float4 ra[4], rw;

    auto LD = [&](int c){
        const int k0c = c * KC;
#pragma unroll
        for (int j = 0; j < 4; j++){
            int f = tid + 256*j; int row = f >> 3, q = f & 7;
            ra[j] = __ldg((const float4*)(x + (size_t)(t0 + row) * Dq + k0c) + q);
        }
        rw = __ldg((const float4*)(W1 + (size_t)(tid >> 3) * Dq + k0c) + (tid & 7));
    };
    auto ST = [&](int buf){
        const uint32_t stg = O_STAGE + buf * STG_SZ;
#pragma unroll
        for (int j = 0; j < 4; j++){
            int f = tid + 256*j; int row = f >> 3, q = f & 7;
            float4 v = ra[j];
            uint32_t h0 = bf2pack(v.x, v.y), h1 = bf2pack(v.z, v.w);
            float hx = __uint_as_float(h0 << 16), hy = __uint_as_float(h0 & 0xffff0000u);
            float hz = __uint_as_float(h1 << 16), hw = __uint_as_float(h1 & 0xffff0000u);
            uint32_t l0 = bf2pack(v.x - hx, v.y - hy), l1 = bf2pack(v.z - hz, v.w - hw);
            uint32_t bo = SWZ64((uint32_t)(row * 64 + q * 8));
            *(uint2*)(smem + stg + S_AH + bo) = make_uint2(h0, h1);
            *(uint2*)(smem + stg + S_AL + bo) = make_uint2(l0, l1);
        }
        {
            int row = tid >> 3, q = tid & 7;
            float4 v = rw;
            uint32_t h0 = bf2pack(v.x, v.y), h1 = bf2pack(v.z, v.w);
            float hx = __uint_as_float(h0 << 16), hy = __uint_as_float(h0 & 0xffff0000u);
            float hz = __uint_as_float(h1 << 16), hw = __uint_as_float(h1 & 0xffff0000u);
            uint32_t l0 = bf2pack(v.x - hx, v.y - hy), l1 = bf2pack(v.z - hz, v.w - hw);
            uint32_t bo = SWZ64((uint32_t)(row * 64 + q * 8));
            *(uint2*)(smem + stg + S_BH + bo) = make_uint2(h0, h1);
            *(uint2*)(smem + stg + S_BL + bo) = make_uint2(l0, l1);
        }
    };

    LD(0);
    ST(0);
    __syncthreads();

    float acc[4][4];
#pragma unroll
    for (int i = 0; i < 4; i++)
#pragma unroll
        for (int j = 0; j < 4; j++) acc[i][j] = 0.f;

    const int arow = wid * 16 + (lid & 15);
    const int bn   = (lid & 7) + ((lid >> 4) * 8);

    for (int c = 0; c < NCHK; c++){
        if (c + 1 < NCHK) LD(c + 1);
        const uint32_t stg = O_STAGE + (c & 1) * STG_SZ;
#pragma unroll
        for (int k = 0; k < 2; k++){
            uint32_t ah[4], al[4];
            uint32_t ab = SWZ64((uint32_t)(arow * 64 + k * 32 + ((lid >> 4) * 16)));
            ldsm4(sb + stg + S_AH + ab, ah);
            ldsm4(sb + stg + S_AL + ab, al);
            const uint32_t kb = (uint32_t)(k * 32 + ((lid >> 3) & 1) * 16);
#pragma unroll
            for (int nb2 = 0; nb2 < 2; nb2++){
                uint32_t bh[4], bl[4];
                uint32_t bb = SWZ64((uint32_t)((nb2 * 16 + bn) * 64) + kb);
                ldsm4(sb + stg + S_BH + bb, bh);
                ldsm4(sb + stg + S_BL + bb, bl);
                mma16816(acc[nb2*2],   ah, bh[0], bh[1]);
                mma16816(acc[nb2*2+1], ah, bh[2], bh[3]);
                mma16816(acc[nb2*2],   ah, bl[0], bl[1]);
                mma16816(acc[nb2*2+1], ah, bl[2], bl[3]);
                mma16816(acc[nb2*2],   al, bh[0], bh[1]);
                mma16816(acc[nb2*2+1], al, bh[2], bh[3]);
            }
        }
        if (c + 1 < NCHK){
            ST((c + 1) & 1);
            __syncthreads();
        }
    }

    // h1 (pre-bias) -> smem; h1s (16.9 KB) fits inside stage buf0 (20.5 KB) and the
    // loop's final barrier (after ST of chunk 31) already drained buf0 readers.
    float* h1s = (float*)(smem + O_STAGE);
    {
        const int gid = lid >> 2, qd = lid & 3;
        const int r0 = wid * 16 + gid, r1 = r0 + 8;
#pragma unroll
        for (int nbl = 0; nbl < 4; nbl++){
            h1s[r0*33 + nbl*8 + qd*2 + 0] = acc[nbl][0];
            h1s[r0*33 + nbl*8 + qd*2 + 1] = acc[nbl][1];
            h1s[r1*33 + nbl*8 + qd*2 + 0] = acc[nbl][2];
            h1s[r1*33 + nbl*8 + qd*2 + 1] = acc[nbl][3];
        }
    }
    __syncthreads();

    if (tid < MT){
        const int m = tid;
        const size_t t = (size_t)t0 + m;
        float hv[32];
#pragma unroll
        for (int h = 0; h < 32; h++){
            float v = h1s[m*33 + h] + sf[F_B1 + h];
            hv[h] = v > 0.f ? v : 0.f;
        }
        float h2[8];
#pragma unroll
        for (int g = 0; g < 8; g++){
            float s = sf[F_B2 + g];
#pragma unroll
            for (int h = 0; h < 32; h++) s = fmaf(sf[F_W2 + g*32 + h], hv[h], s);
            h2[g] = s > 0.f ? s : 0.f;
        }
        float sc = sf[F_BSC];
#pragma unroll
        for (int h4 = 0; h4 < 8; h4++){
            float4 o4; float* op = &o4.x;
#pragma unroll
            for (int kk = 0; kk < 4; kk++){
                const int h = h4*4 + kk;
                float s = sf[F_B3 + h];
#pragma unroll
                for (int g = 0; g < 8; g++) s = fmaf(sf[F_W3 + h*8 + g], h2[g], s);
                s = s > 0.f ? s : 0.f;
                op[kk] = s;
                sc = fmaf(sf[F_WSC + h], s, sc);
            }
            *(float4*)(&g_outv[t*32 + h4*4]) = o4;
        }
        g_scores[t] = sc > 0.f ? sc : 0.f;
    }
}

// ======= Kernel 2a: slice-local stable top/bottom-10 candidates ===================
// Key = (score_bits << 32) | index == jnp.argsort stable (score, index) order.
__global__ __launch_bounds__(256) void k2a(){
    const int bx = blockIdx.x;
    const int b = bx / SPL, sl = bx % SPL;
    const int tid = threadIdx.x, lane = tid & 31, warp = tid >> 5;  // 8 warps
    __shared__ unsigned long long wred[8], swin, skB[KSEL], skT[KSEL];

    unsigned long long bot[KSEL], top[KSEL];
#pragma unroll
    for (int j = 0; j < KSEL; j++){ bot[j] = ~0ull; top[j] = 0ull; }

    const float4* sp = (const float4*)(g_scores + (size_t)b * Nq + sl * SLE);
    for (int v = tid; v < SLE/4; v += 256){
        float4 s4 = sp[v];
        float ss[4] = {s4.x, s4.y, s4.z, s4.w};
#pragma unroll
        for (int e = 0; e < 4; e++){
            unsigned long long key = ((unsigned long long)__float_as_uint(ss[e]) << 32)
                                   | (unsigned)(sl*SLE + v*4 + e);
            if (key < bot[KSEL-1]){
                bot[KSEL-1] = key;
#pragma unroll
                for (int j = KSEL-1; j > 0; j--){
                    unsigned long long a0 = bot[j-1], a1 = bot[j];
                    bot[j-1] = a0 < a1 ? a0 : a1;
                    bot[j]   = a0 < a1 ? a1 : a0;
                }
            }
            if (key > top[KSEL-1]){
                top[KSEL-1] = key;
#pragma unroll
                for (int j = KSEL-1; j > 0; j--){
                    unsigned long long a0 = top[j-1], a1 = top[j];
                    top[j-1] = a0 > a1 ? a0 : a1;
                    top[j]   = a0 > a1 ? a1 : a0;
                }
            }
        }
    }
    __syncthreads();

    for (int i = 0; i < KSEL; i++){
        unsigned long long v = bot[0];
#pragma unroll
        for (int o = 16; o > 0; o >>= 1){
            unsigned long long u = __shfl_down_sync(0xffffffffu, v, o);
            if (u < v) v = u;
        }
        if (lane == 0) wred[warp] = v;
        __syncthreads();
        if (warp == 0){
            unsigned long long w = (lane < 8) ? wred[lane] : ~0ull;
#pragma unroll
            for (int o = 4; o > 0; o >>= 1){
                unsigned long long u = __shfl_down_sync(0xffffffffu, w, o);
                if (u < w) w = u;
            }
            if (lane == 0){ swin = w; skB[i] = w; }
        }
        __syncthreads();
        if (bot[0] == swin){
#pragma unroll
            for (int j = 0; j < KSEL-1; j++) bot[j] = bot[j+1];
            bot[KSEL-1] = ~0ull;
        }
        __syncthreads();
    }
    for (int i = 0; i < KSEL; i++){
        unsigned long long v = top[0];
#pragma unroll
        for (int o = 16; o > 0; o >>= 1){
            unsigned long long u = __shfl_down_sync(0xffffffffu, v, o);
            if (u > v) v = u;
        }
        if (lane == 0) wred[warp] = v;
        __syncthreads();
        if (warp == 0){
            unsigned long long w = (lane < 8) ? wred[lane] : 0ull;
#pragma unroll
            for (int o = 4; o > 0; o >>= 1){
                unsigned long long u = __shfl_down_sync(0xffffffffu, w, o);
                if (u > w) w = u;
            }
            if (lane == 0){ swin = w; skT[i] = w; }
        }
        __syncthreads();
        if (top[0] == swin){
#pragma unroll
            for (int j = 0; j < KSEL-1; j++) top[j] = top[j+1];
            top[KSEL-1] = 0ull;
        }
        __syncthreads();
    }
    if (tid < KSEL){ g_candB[b][sl][tid] = skB[tid]; g_candT[b][sl][tid] = skT[tid]; }
}

// ======= Kernel 2b: single-warp register merges + gather + classifier =============
// Warp 0 merges the 100 bottom candidates, warp 1 the 100 top candidates, entirely
// in registers with shfl butterflies (no block barriers). Wc1 cp.async prefetch
// overlaps the merges.
__global__ __launch_bounds__(256) void k2b(
    const float* __restrict__ Wc1, const float* __restrict__ bc1,
    const float* __restrict__ Wc2, const float* __restrict__ bc2,
    const float* __restrict__ Wc3, const float* __restrict__ bc3,
    float* __restrict__ outp)
{
    extern __shared__ float dsm[];
    float* sWc1 = dsm;                 // 22144 floats
    const int b = blockIdx.x, tid = threadIdx.x;
    const int lane = tid & 31, warp = tid >> 5;
    __shared__ unsigned long long selkey[20];
    __shared__ float feat[692], z1[32], z2[32];

    // prefetch Wc1: 5536 x 16B segments (overlaps the merge phase)
    {
        const uint32_t dst = s2u(sWc1);
        for (int i = tid; i < 5536; i += 256)
            cp16(dst + i*16, Wc1 + i*4);
        asm volatile("cp.async.commit_group;" ::: "memory");
    }

    if (warp == 0){
        // bottom merge: 100 keys, 4 per lane (pad ~0)
        const unsigned long long* cb = &g_candB[b][0][0];
        unsigned long long c0 = cb[lane];
        unsigned long long c1 = cb[lane + 32];
        unsigned long long c2 = cb[lane + 64];
        unsigned long long c3 = (lane < 4) ? cb[lane + 96] : ~0ull;
#pragma unroll
        for (int i = 0; i < KSEL; i++){
            unsigned long long v = c0 < c1 ? c0 : c1;
            unsigned long long w = c2 < c3 ? c2 : c3;
            v = v < w ? v : w;
#pragma unroll
            for (int o = 16; o > 0; o >>= 1){
                unsigned long long u = __shfl_xor_sync(0xffffffffu, v, o);
                if (u < v) v = u;
            }
            if (lane == 0) selkey[i] = v;
            if (c0 == v) c0 = ~0ull;
            if (c1 == v) c1 = ~0ull;
            if (c2 == v) c2 = ~0ull;
            if (c3 == v) c3 = ~0ull;
        }
    } else if (warp == 1){
        // top merge: extract maxima descending -> selkey[19-i]
        const unsigned long long* ct = &g_candT[b][0][0];
        unsigned long long c0 = ct[lane];
        unsigned long long c1 = ct[lane + 32];
        unsigned long long c2 = ct[lane + 64];
        unsigned long long c3 = (lane < 4) ? ct[lane + 96] : 0ull;
#pragma unroll
        for (int i = 0; i < KSEL; i++){
            unsigned long long v = c0 > c1 ? c0 : c1;
            unsigned long long w = c2 > c3 ? c2 : c3;
            v = v > w ? v : w;
#pragma unroll
            for (int o = 16; o > 0; o >>= 1){
                unsigned long long u = __shfl_xor_sync(0xffffffffu, v, o);
                if (u > v) v = u;
            }
            if (lane == 0) selkey[19 - i] = v;
            if (c0 == v) c0 = 0ull;
            if (c1 == v) c1 = 0ull;
            if (c2 == v) c2 = 0ull;
            if (c3 == v) c3 = 0ull;
        }
    }
    __syncthreads();

    // features: [g_sc(0..19) | avg(20..51) | g_flat(52..691): 52 + h*20 + j]
    for (int i = tid; i < 640; i += 256){
        int j = i >> 5, h = i & 31;
        int n = (int)(selkey[j] & 0xFFFFFFFFull);
        feat[52 + h*20 + j] = g_outv[((size_t)b*Nq + n)*32 + h];
    }
    if (tid < 20) feat[tid] = __uint_as_float((unsigned)(selkey[tid] >> 32));
    __syncthreads();
    if (tid < 32){
        float s = 0.f;
#pragma unroll
        for (int j = 0; j < 20; j++) s += feat[52 + tid*20 + j];
        feat[20 + tid] = s * (1.f/20.f);
    }
    asm volatile("cp.async.wait_group 0;" ::: "memory");
    __syncthreads();

    // classifier layer 1 from smem: 8 threads per output + shfl reduce
    {
        int o = tid >> 3, p = tid & 7;
        const float* wr = sWc1 + o * 692;
        float s = 0.f;
        for (int i = p; i < 692; i += 8) s = fmaf(wr[i], feat[i], s);
        s += __shfl_xor_sync(0xffffffffu, s, 1);
        s += __shfl_xor_sync(0xffffffffu, s, 2);
        s += __shfl_xor_sync(0xffffffffu, s, 4);
        if (p == 0){ s += bc1[o]; z1[o] = s > 0.f ? s : 0.f; }
    }
    __syncthreads();
    if (tid < 32){
        float s = bc2[tid];
#pragma unroll
        for (int i = 0; i < 32; i++) s = fmaf(Wc2[tid*32+i], z1[i], s);
        z2[tid] = s > 0.f ? s : 0.f;
    }
    __syncthreads();
    if (tid == 0){
        float s = bc3[0];
#pragma unroll
        for (int i = 0; i < 32; i++) s = fmaf(Wc3[i], z2[i], s);
        outp[b] = 1.f / (1.f + expf(-s));
    }
}

extern "C" void kernel_launch(void* const* d_in, const int* in_sizes, int n_in,
                              void* d_out, int out_size) {
    const float* x   = (const float*)d_in[0];
    const float* W1  = (const float*)d_in[1];
    const float* b1  = (const float*)d_in[2];
    const float* W2  = (const float*)d_in[3];
    const float* b2  = (const float*)d_in[4];
    const float* W3  = (const float*)d_in[5];
    const float* b3  = (const float*)d_in[6];
    const float* Wsc = (const float*)d_in[7];
    const float* bsc = (const float*)d_in[8];
    const float* Wc1 = (const float*)d_in[9];
    const float* bc1 = (const float*)d_in[10];
    const float* Wc2 = (const float*)d_in[11];
    const float* bc2 = (const float*)d_in[12];
    const float* Wc3 = (const float*)d_in[13];
    const float* bc3 = (const float*)d_in[14];
    float* outp = (float*)d_out;

    cudaFuncSetAttribute(k1,  cudaFuncAttributeMaxDynamicSharedMemorySize, SMEM_K1);
    cudaFuncSetAttribute(k2b, cudaFuncAttributeMaxDynamicSharedMemorySize, SMEM_K2B);
    k1<<<NT/MT, 256, SMEM_K1>>>(x, W1, b1, W2, b2, W3, b3, Wsc, bsc);
    k2a<<<Bq*SPL, 256>>>();
    k2b<<<Bq, 256, SMEM_K2B>>>(Wc1, bc1, Wc2, bc2, Wc3, bc3, outp);
}